// round 1
// baseline (speedup 1.0000x reference)
#include <cuda_runtime.h>
#include <math.h>

#define NN 2048
#define NE 32768
#define HD 128

// ---------------- scratch (static __device__, no allocation) ----------------
__device__ int   g_adj[NN * NN];        // winning edge index per (src,dst), -1 if none (16.8 MB)
__device__ int   g_deg_src[NN];
__device__ int   g_cnt_dst[NN];
__device__ int   g_off_src[NN + 1];
__device__ int   g_off_dst[NN + 1];
__device__ int   g_cur_src[NN];
__device__ int   g_cur_dst[NN];
__device__ int   g_nb_col[NE];          // dedup'd out-neighbor cols per src
__device__ float g_nb_val[NE];          // corresponding adj value (winner's dist)
__device__ int   g_in_edge[NE];         // CSR by dst: incoming edge ids (all edges)
__device__ float g_A[NN * HD];          // mu@W1_mu + sigma@W1_sig + b1  (per node)
__device__ float g_res[NE];
__device__ float g_wgt[NE];             // exp(-residual)
__device__ float g_wm[NE * HD];         // weighted messages (16.8 MB)
__device__ float g_agg[NN * HD];
__device__ float g_meanr[NN];

// ---------------- 1: init ----------------
__global__ void k_init() {
    int i = blockIdx.x * blockDim.x + threadIdx.x;
    if (i < NN * NN) g_adj[i] = -1;
    if (i < NN) { g_deg_src[i] = 0; g_cnt_dst[i] = 0; g_cur_src[i] = 0; g_cur_dst[i] = 0; }
}

// ---------------- 2: scatter with last-write-wins (max edge index) ----------------
__global__ void k_scatter(const int* __restrict__ ei) {
    int e = blockIdx.x * blockDim.x + threadIdx.x;
    if (e >= NE) return;
    int s = ei[e], d = ei[NE + e];
    atomicMax(&g_adj[s * NN + d], e);
}

// ---------------- 3: degree counts ----------------
__global__ void k_count(const int* __restrict__ ei) {
    int e = blockIdx.x * blockDim.x + threadIdx.x;
    if (e >= NE) return;
    int s = ei[e], d = ei[NE + e];
    if (g_adj[s * NN + d] == e) atomicAdd(&g_deg_src[s], 1);
    atomicAdd(&g_cnt_dst[d], 1);
}

// ---------------- 4: prefix scans (serial; N=2048, negligible) ----------------
__global__ void k_scan() {
    if (threadIdx.x == 0) {
        int a = 0; g_off_src[0] = 0;
        for (int i = 0; i < NN; i++) { a += g_deg_src[i]; g_off_src[i + 1] = a; }
    }
    if (threadIdx.x == 1) {
        int a = 0; g_off_dst[0] = 0;
        for (int i = 0; i < NN; i++) { a += g_cnt_dst[i]; g_off_dst[i + 1] = a; }
    }
}

// ---------------- 5: fill CSRs ----------------
__global__ void k_fill(const int* __restrict__ ei, const float* __restrict__ dist) {
    int e = blockIdx.x * blockDim.x + threadIdx.x;
    if (e >= NE) return;
    int s = ei[e], d = ei[NE + e];
    if (g_adj[s * NN + d] == e) {
        int p = atomicAdd(&g_cur_src[s], 1);
        int o = g_off_src[s] + p;
        g_nb_col[o] = d;
        g_nb_val[o] = dist[e];
    }
    int q = atomicAdd(&g_cur_dst[d], 1);
    g_in_edge[g_off_dst[d] + q] = e;
}

// ---------------- 6: per-node layer-1 pre-GEMM: A = mu@W1[0:128] + sigma@W1[128:256] + b1 ----------------
__global__ void __launch_bounds__(128) k_nodeA(const float* __restrict__ mu,
                                               const float* __restrict__ sig,
                                               const float* __restrict__ w1,
                                               const float* __restrict__ b1) {
    __shared__ float xs[16][256];
    int t = threadIdx.x;
    int nb = blockIdx.x * 16;
    #pragma unroll
    for (int i = 0; i < 16; i++) {
        xs[i][t]       = mu[(nb + i) * HD + t];
        xs[i][128 + t] = sig[(nb + i) * HD + t];
    }
    __syncthreads();
    float acc[16];
    float b = b1[t];
    #pragma unroll
    for (int i = 0; i < 16; i++) acc[i] = b;
    #pragma unroll 4
    for (int k = 0; k < 256; k++) {
        float w = __ldg(&w1[k * HD + t]);
        #pragma unroll
        for (int i = 0; i < 16; i++) acc[i] += xs[i][k] * w;
    }
    #pragma unroll
    for (int i = 0; i < 16; i++) g_A[(nb + i) * HD + t] = acc[i];
}

// ---------------- 7: residuals via sparse two-hop probe ----------------
__global__ void k_res(const int* __restrict__ ei, const float* __restrict__ dist,
                      float* __restrict__ out_res) {
    int e = blockIdx.x * blockDim.x + threadIdx.x;
    if (e >= NE) return;
    int s = ei[e], d = ei[NE + e];
    float dac = dist[e];
    int beg = g_off_src[s], end = g_off_src[s + 1];
    float sum = 0.0f; int cnt = 0;
    for (int i = beg; i < end; i++) {
        int B = g_nb_col[i];
        float dab = g_nb_val[i];
        int idx = g_adj[B * NN + d];
        if (idx >= 0) { sum += dab + dist[idx]; cnt++; }
    }
    float mean = (cnt > 0) ? (sum / (float)cnt) : dac;
    float r = fabsf(dac - mean);
    g_res[e] = r;
    g_wgt[e] = expf(-r);
    out_res[e] = r;
}

// ---------------- 8: edge hidden + layer-2 GEMM + weighting ----------------
// 32 edges per block. hid stored transposed [j][e] with pad 36 so stage-2 reads are
// float4 broadcasts (crossbar-friendly); W2 streamed through L1/L2.
__global__ void __launch_bounds__(128) k_edge(const int* __restrict__ ei,
                                              const float* __restrict__ dist,
                                              const float* __restrict__ conf,
                                              const float* __restrict__ ang,
                                              const float* __restrict__ dep,
                                              const float* __restrict__ w1,
                                              const float* __restrict__ w2,
                                              const float* __restrict__ b2) {
    __shared__ float hidT[128 * 36];   // [j][e], row stride 36 (16B-aligned rows, reduced bank conflicts)
    int t = threadIdx.x;
    int eb = blockIdx.x * 32;
    float wf0 = w1[(256) * HD + t];
    float wf1 = w1[(257) * HD + t];
    float wf2 = w1[(258) * HD + t];
    float wf3 = w1[(259) * HD + t];
    #pragma unroll 4
    for (int x = 0; x < 32; x++) {
        int e = eb + x;
        int s = ei[e];
        float v = g_A[s * HD + t]
                + dist[e] * wf0 + conf[e] * wf1 + ang[e] * wf2 + dep[e] * wf3;
        hidT[t * 36 + x] = fmaxf(v, 0.0f);
    }
    __syncthreads();

    float acc[32];
    #pragma unroll
    for (int x = 0; x < 32; x++) acc[x] = 0.0f;

    #pragma unroll 4
    for (int j = 0; j < 128; j++) {
        float w = __ldg(&w2[j * HD + t]);
        const float4* hp = (const float4*)(&hidT[j * 36]);
        #pragma unroll
        for (int x4 = 0; x4 < 8; x4++) {
            float4 h4 = hp[x4];
            acc[4 * x4 + 0] += h4.x * w;
            acc[4 * x4 + 1] += h4.y * w;
            acc[4 * x4 + 2] += h4.z * w;
            acc[4 * x4 + 3] += h4.w * w;
        }
    }
    float bb = b2[t];
    #pragma unroll
    for (int x = 0; x < 32; x++) {
        int e = eb + x;
        g_wm[e * HD + t] = (acc[x] + bb) * g_wgt[e];
    }
}

// ---------------- 9: deterministic segment aggregation by dst ----------------
__global__ void __launch_bounds__(128) k_agg() {
    int n = blockIdx.x;
    int t = threadIdx.x;
    int beg = g_off_dst[n], end = g_off_dst[n + 1];
    float acc = 0.0f, ws = 0.0f, rs = 0.0f;
    for (int i = beg; i < end; i++) {
        int e = g_in_edge[i];
        acc += g_wm[e * HD + t];
        ws  += g_wgt[e];
        rs  += g_res[e];
    }
    g_agg[n * HD + t] = acc / fmaxf(ws, 1e-8f);
    if (t == 0) g_meanr[n] = rs / fmaxf((float)(end - beg), 1.0f);
}

// ---------------- 10: node MLPs (mu update + sigma softplus head) ----------------
__global__ void __launch_bounds__(128) k_node(const float* __restrict__ mu,
                                              const float* __restrict__ muw1, const float* __restrict__ mub1,
                                              const float* __restrict__ muw2, const float* __restrict__ mub2,
                                              const float* __restrict__ sgw1, const float* __restrict__ sgb1,
                                              const float* __restrict__ sgw2, const float* __restrict__ sgb2,
                                              float* __restrict__ out) {
    __shared__ float xs[16][128];
    __shared__ float ys[16][128];
    __shared__ float mr[16];
    int t = threadIdx.x;
    int nb = blockIdx.x * 16;
    #pragma unroll
    for (int i = 0; i < 16; i++) xs[i][t] = g_agg[(nb + i) * HD + t];
    if (t < 16) mr[t] = g_meanr[nb + t];
    __syncthreads();

    float acc[16];

    // mu hidden
    { float b = mub1[t];
      #pragma unroll
      for (int i = 0; i < 16; i++) acc[i] = b;
      #pragma unroll 4
      for (int k = 0; k < 128; k++) {
          float w = __ldg(&muw1[k * HD + t]);
          #pragma unroll
          for (int i = 0; i < 16; i++) acc[i] += xs[i][k] * w;
      } }
    #pragma unroll
    for (int i = 0; i < 16; i++) ys[i][t] = fmaxf(acc[i], 0.0f);
    __syncthreads();

    // mu out
    { float b = mub2[t];
      #pragma unroll
      for (int i = 0; i < 16; i++) acc[i] = b;
      #pragma unroll 4
      for (int k = 0; k < 128; k++) {
          float w = __ldg(&muw2[k * HD + t]);
          #pragma unroll
          for (int i = 0; i < 16; i++) acc[i] += ys[i][k] * w;
      }
      #pragma unroll
      for (int i = 0; i < 16; i++)
          out[(nb + i) * HD + t] = mu[(nb + i) * HD + t] + acc[i];
    }

    // sigma hidden (129-dim input: agg + mean_r)
    { float b = sgb1[t];
      float wlast = __ldg(&sgw1[128 * HD + t]);
      #pragma unroll
      for (int i = 0; i < 16; i++) acc[i] = b + mr[i] * wlast;
      #pragma unroll 4
      for (int k = 0; k < 128; k++) {
          float w = __ldg(&sgw1[k * HD + t]);
          #pragma unroll
          for (int i = 0; i < 16; i++) acc[i] += xs[i][k] * w;
      } }
    __syncthreads();   // mu-out pass done reading ys
    #pragma unroll
    for (int i = 0; i < 16; i++) ys[i][t] = fmaxf(acc[i], 0.0f);
    __syncthreads();

    // sigma out + softplus
    { float b = sgb2[t];
      #pragma unroll
      for (int i = 0; i < 16; i++) acc[i] = b;
      #pragma unroll 4
      for (int k = 0; k < 128; k++) {
          float w = __ldg(&sgw2[k * HD + t]);
          #pragma unroll
          for (int i = 0; i < 16; i++) acc[i] += ys[i][k] * w;
      }
      #pragma unroll
      for (int i = 0; i < 16; i++) {
          float x = acc[i];
          float sp = fmaxf(x, 0.0f) + log1pf(expf(-fabsf(x)));
          out[NN * HD + (nb + i) * HD + t] = sp;
      } }
}

// ---------------- launch ----------------
extern "C" void kernel_launch(void* const* d_in, const int* in_sizes, int n_in,
                              void* d_out, int out_size) {
    const float* mu    = (const float*)d_in[0];
    const float* sigma = (const float*)d_in[1];
    const int*   ei    = (const int*)d_in[2];
    const float* dist  = (const float*)d_in[3];
    const float* conf  = (const float*)d_in[4];
    const float* ang   = (const float*)d_in[5];
    const float* dep   = (const float*)d_in[6];
    const float* msgw1 = (const float*)d_in[7];
    const float* msgb1 = (const float*)d_in[8];
    const float* msgw2 = (const float*)d_in[9];
    const float* msgb2 = (const float*)d_in[10];
    const float* muw1  = (const float*)d_in[11];
    const float* mub1  = (const float*)d_in[12];
    const float* muw2  = (const float*)d_in[13];
    const float* mub2  = (const float*)d_in[14];
    const float* sgw1  = (const float*)d_in[15];
    const float* sgb1  = (const float*)d_in[16];
    const float* sgw2  = (const float*)d_in[17];
    const float* sgb2  = (const float*)d_in[18];
    float* out = (float*)d_out;

    float* out_res = out + 2 * NN * HD;   // layout: mu_new | sigma_new | residuals

    k_init<<<(NN * NN + 255) / 256, 256>>>();
    k_scatter<<<NE / 256, 256>>>(ei);
    k_count<<<NE / 256, 256>>>(ei);
    k_scan<<<1, 32>>>();
    k_fill<<<NE / 256, 256>>>(ei, dist);
    k_nodeA<<<NN / 16, 128>>>(mu, sigma, msgw1, msgb1);
    k_res<<<NE / 256, 256>>>(ei, dist, out_res);
    k_edge<<<NE / 32, 128>>>(ei, dist, conf, ang, dep, msgw1, msgw2, msgb2);
    k_agg<<<NN, 128>>>();
    k_node<<<NN / 16, 128>>>(mu, muw1, mub1, muw2, mub2, sgw1, sgb1, sgw2, sgb2, out);
}

// round 2
// speedup vs baseline: 2.2724x; 2.2724x over previous
#include <cuda_runtime.h>
#include <math.h>

#define NN 2048
#define NE 32768
#define HD 128

// ---------------- scratch (static __device__, no allocation) ----------------
__device__ int   g_adj[NN * NN];        // winning edge index per (src,dst), -1 if none (16.8 MB)
__device__ int   g_deg_src[NN];
__device__ int   g_cnt_dst[NN];
__device__ int   g_off_src[NN + 1];
__device__ int   g_off_dst[NN + 1];
__device__ int   g_cur_src[NN];
__device__ int   g_cur_dst[NN];
__device__ int   g_nb_col[NE];          // dedup'd out-neighbor cols per src
__device__ float g_nb_val[NE];          // corresponding adj value (winner's dist)
__device__ int   g_in_edge[NE];         // CSR by dst: incoming edge ids (all edges)
__device__ float g_A[NN * HD];          // mu@W1_mu + sigma@W1_sig + b1  (per node)
__device__ float g_res[NE];
__device__ float g_wgt[NE];             // exp(-residual)
__device__ float g_wm[NE * HD];         // weighted messages (16.8 MB)
__device__ float g_agg[NN * HD];
__device__ float g_meanr[NN];

// ---------------- 1: init ----------------
__global__ void k_init() {
    int i = blockIdx.x * blockDim.x + threadIdx.x;
    if (i < NN * NN) g_adj[i] = -1;
    if (i < NN) { g_deg_src[i] = 0; g_cnt_dst[i] = 0; g_cur_src[i] = 0; g_cur_dst[i] = 0; }
}

// ---------------- 2: scatter with last-write-wins (max edge index) ----------------
__global__ void k_scatter(const int* __restrict__ ei) {
    int e = blockIdx.x * blockDim.x + threadIdx.x;
    if (e >= NE) return;
    int s = ei[e], d = ei[NE + e];
    atomicMax(&g_adj[s * NN + d], e);
}

// ---------------- 3: degree counts ----------------
__global__ void k_count(const int* __restrict__ ei) {
    int e = blockIdx.x * blockDim.x + threadIdx.x;
    if (e >= NE) return;
    int s = ei[e], d = ei[NE + e];
    if (g_adj[s * NN + d] == e) atomicAdd(&g_deg_src[s], 1);
    atomicAdd(&g_cnt_dst[d], 1);
}

// ---------------- 4: parallel prefix scan (2 blocks: src + dst) ----------------
// 1024 threads/block, each owns 2 contiguous elements of a 2048-vector.
__global__ void __launch_bounds__(1024) k_scan() {
    const int* in = blockIdx.x ? g_cnt_dst : g_deg_src;
    int* off      = blockIdx.x ? g_off_dst : g_off_src;
    int t = threadIdx.x;
    int a = in[2 * t], b = in[2 * t + 1];
    int s = a + b;

    int lane = t & 31, wid = t >> 5;
    int v = s;
    #pragma unroll
    for (int o = 1; o < 32; o <<= 1) {
        int n = __shfl_up_sync(0xffffffffu, v, o);
        if (lane >= o) v += n;
    }
    __shared__ int wsum[32];
    if (lane == 31) wsum[wid] = v;
    __syncthreads();
    if (wid == 0) {
        int w = wsum[lane];
        #pragma unroll
        for (int o = 1; o < 32; o <<= 1) {
            int n = __shfl_up_sync(0xffffffffu, w, o);
            if (lane >= o) w += n;
        }
        wsum[lane] = w;
    }
    __syncthreads();
    int incl = v + (wid ? wsum[wid - 1] : 0);   // inclusive scan of pair-sums
    int excl = incl - s;                        // exclusive prefix of element 2t
    off[2 * t]     = excl;
    off[2 * t + 1] = excl + a;
    if (t == 1023) off[2048] = incl;
}

// ---------------- 5: fill CSRs ----------------
__global__ void k_fill(const int* __restrict__ ei, const float* __restrict__ dist) {
    int e = blockIdx.x * blockDim.x + threadIdx.x;
    if (e >= NE) return;
    int s = ei[e], d = ei[NE + e];
    if (g_adj[s * NN + d] == e) {
        int p = atomicAdd(&g_cur_src[s], 1);
        int o = g_off_src[s] + p;
        g_nb_col[o] = d;
        g_nb_val[o] = dist[e];
    }
    int q = atomicAdd(&g_cur_dst[d], 1);
    g_in_edge[g_off_dst[d] + q] = e;
}

// ---------------- 6: per-node layer-1 pre-GEMM: A = mu@W1[0:128] + sigma@W1[128:256] + b1 ----------------
__global__ void __launch_bounds__(128) k_nodeA(const float* __restrict__ mu,
                                               const float* __restrict__ sig,
                                               const float* __restrict__ w1,
                                               const float* __restrict__ b1) {
    __shared__ float xs[16][256];
    int t = threadIdx.x;
    int nb = blockIdx.x * 16;
    #pragma unroll
    for (int i = 0; i < 16; i++) {
        xs[i][t]       = mu[(nb + i) * HD + t];
        xs[i][128 + t] = sig[(nb + i) * HD + t];
    }
    __syncthreads();
    float acc[16];
    float b = b1[t];
    #pragma unroll
    for (int i = 0; i < 16; i++) acc[i] = b;
    #pragma unroll 4
    for (int k = 0; k < 256; k++) {
        float w = __ldg(&w1[k * HD + t]);
        #pragma unroll
        for (int i = 0; i < 16; i++) acc[i] += xs[i][k] * w;
    }
    #pragma unroll
    for (int i = 0; i < 16; i++) g_A[(nb + i) * HD + t] = acc[i];
}

// ---------------- 7: residuals via sparse two-hop probe ----------------
__global__ void k_res(const int* __restrict__ ei, const float* __restrict__ dist,
                      float* __restrict__ out_res) {
    int e = blockIdx.x * blockDim.x + threadIdx.x;
    if (e >= NE) return;
    int s = ei[e], d = ei[NE + e];
    float dac = dist[e];
    int beg = g_off_src[s], end = g_off_src[s + 1];
    float sum = 0.0f; int cnt = 0;
    for (int i = beg; i < end; i++) {
        int B = g_nb_col[i];
        float dab = g_nb_val[i];
        int idx = g_adj[B * NN + d];
        if (idx >= 0) { sum += dab + dist[idx]; cnt++; }
    }
    float mean = (cnt > 0) ? (sum / (float)cnt) : dac;
    float r = fabsf(dac - mean);
    g_res[e] = r;
    g_wgt[e] = expf(-r);
    out_res[e] = r;
}

// ---------------- 8: edge hidden + layer-2 GEMM + weighting ----------------
__global__ void __launch_bounds__(128) k_edge(const int* __restrict__ ei,
                                              const float* __restrict__ dist,
                                              const float* __restrict__ conf,
                                              const float* __restrict__ ang,
                                              const float* __restrict__ dep,
                                              const float* __restrict__ w1,
                                              const float* __restrict__ w2,
                                              const float* __restrict__ b2) {
    __shared__ float hidT[128 * 36];   // [j][e], row stride 36
    int t = threadIdx.x;
    int eb = blockIdx.x * 32;
    float wf0 = w1[(256) * HD + t];
    float wf1 = w1[(257) * HD + t];
    float wf2 = w1[(258) * HD + t];
    float wf3 = w1[(259) * HD + t];
    #pragma unroll 4
    for (int x = 0; x < 32; x++) {
        int e = eb + x;
        int s = ei[e];
        float v = g_A[s * HD + t]
                + dist[e] * wf0 + conf[e] * wf1 + ang[e] * wf2 + dep[e] * wf3;
        hidT[t * 36 + x] = fmaxf(v, 0.0f);
    }
    __syncthreads();

    float acc[32];
    #pragma unroll
    for (int x = 0; x < 32; x++) acc[x] = 0.0f;

    #pragma unroll 4
    for (int j = 0; j < 128; j++) {
        float w = __ldg(&w2[j * HD + t]);
        const float4* hp = (const float4*)(&hidT[j * 36]);
        #pragma unroll
        for (int x4 = 0; x4 < 8; x4++) {
            float4 h4 = hp[x4];
            acc[4 * x4 + 0] += h4.x * w;
            acc[4 * x4 + 1] += h4.y * w;
            acc[4 * x4 + 2] += h4.z * w;
            acc[4 * x4 + 3] += h4.w * w;
        }
    }
    float bb = b2[t];
    #pragma unroll
    for (int x = 0; x < 32; x++) {
        int e = eb + x;
        g_wm[e * HD + t] = (acc[x] + bb) * g_wgt[e];
    }
}

// ---------------- 9: deterministic segment aggregation by dst ----------------
__global__ void __launch_bounds__(128) k_agg() {
    int n = blockIdx.x;
    int t = threadIdx.x;
    int beg = g_off_dst[n], end = g_off_dst[n + 1];
    float acc = 0.0f, ws = 0.0f, rs = 0.0f;
    for (int i = beg; i < end; i++) {
        int e = g_in_edge[i];
        acc += g_wm[e * HD + t];
        ws  += g_wgt[e];
        rs  += g_res[e];
    }
    g_agg[n * HD + t] = acc / fmaxf(ws, 1e-8f);
    if (t == 0) g_meanr[n] = rs / fmaxf((float)(end - beg), 1.0f);
}

// ---------------- 10: node MLPs (mu update + sigma softplus head) ----------------
__global__ void __launch_bounds__(128) k_node(const float* __restrict__ mu,
                                              const float* __restrict__ muw1, const float* __restrict__ mub1,
                                              const float* __restrict__ muw2, const float* __restrict__ mub2,
                                              const float* __restrict__ sgw1, const float* __restrict__ sgb1,
                                              const float* __restrict__ sgw2, const float* __restrict__ sgb2,
                                              float* __restrict__ out) {
    __shared__ float xs[16][128];
    __shared__ float ys[16][128];
    __shared__ float mr[16];
    int t = threadIdx.x;
    int nb = blockIdx.x * 16;
    #pragma unroll
    for (int i = 0; i < 16; i++) xs[i][t] = g_agg[(nb + i) * HD + t];
    if (t < 16) mr[t] = g_meanr[nb + t];
    __syncthreads();

    float acc[16];

    // mu hidden
    { float b = mub1[t];
      #pragma unroll
      for (int i = 0; i < 16; i++) acc[i] = b;
      #pragma unroll 4
      for (int k = 0; k < 128; k++) {
          float w = __ldg(&muw1[k * HD + t]);
          #pragma unroll
          for (int i = 0; i < 16; i++) acc[i] += xs[i][k] * w;
      } }
    #pragma unroll
    for (int i = 0; i < 16; i++) ys[i][t] = fmaxf(acc[i], 0.0f);
    __syncthreads();

    // mu out
    { float b = mub2[t];
      #pragma unroll
      for (int i = 0; i < 16; i++) acc[i] = b;
      #pragma unroll 4
      for (int k = 0; k < 128; k++) {
          float w = __ldg(&muw2[k * HD + t]);
          #pragma unroll
          for (int i = 0; i < 16; i++) acc[i] += ys[i][k] * w;
      }
      #pragma unroll
      for (int i = 0; i < 16; i++)
          out[(nb + i) * HD + t] = mu[(nb + i) * HD + t] + acc[i];
    }

    // sigma hidden (129-dim input: agg + mean_r)
    { float b = sgb1[t];
      float wlast = __ldg(&sgw1[128 * HD + t]);
      #pragma unroll
      for (int i = 0; i < 16; i++) acc[i] = b + mr[i] * wlast;
      #pragma unroll 4
      for (int k = 0; k < 128; k++) {
          float w = __ldg(&sgw1[k * HD + t]);
          #pragma unroll
          for (int i = 0; i < 16; i++) acc[i] += xs[i][k] * w;
      } }
    __syncthreads();   // mu-out pass done reading ys
    #pragma unroll
    for (int i = 0; i < 16; i++) ys[i][t] = fmaxf(acc[i], 0.0f);
    __syncthreads();

    // sigma out + softplus
    { float b = sgb2[t];
      #pragma unroll
      for (int i = 0; i < 16; i++) acc[i] = b;
      #pragma unroll 4
      for (int k = 0; k < 128; k++) {
          float w = __ldg(&sgw2[k * HD + t]);
          #pragma unroll
          for (int i = 0; i < 16; i++) acc[i] += ys[i][k] * w;
      }
      #pragma unroll
      for (int i = 0; i < 16; i++) {
          float x = acc[i];
          float sp = fmaxf(x, 0.0f) + log1pf(expf(-fabsf(x)));
          out[NN * HD + (nb + i) * HD + t] = sp;
      } }
}

// ---------------- launch ----------------
extern "C" void kernel_launch(void* const* d_in, const int* in_sizes, int n_in,
                              void* d_out, int out_size) {
    const float* mu    = (const float*)d_in[0];
    const float* sigma = (const float*)d_in[1];
    const int*   ei    = (const int*)d_in[2];
    const float* dist  = (const float*)d_in[3];
    const float* conf  = (const float*)d_in[4];
    const float* ang   = (const float*)d_in[5];
    const float* dep   = (const float*)d_in[6];
    const float* msgw1 = (const float*)d_in[7];
    const float* msgb1 = (const float*)d_in[8];
    const float* msgw2 = (const float*)d_in[9];
    const float* msgb2 = (const float*)d_in[10];
    const float* muw1  = (const float*)d_in[11];
    const float* mub1  = (const float*)d_in[12];
    const float* muw2  = (const float*)d_in[13];
    const float* mub2  = (const float*)d_in[14];
    const float* sgw1  = (const float*)d_in[15];
    const float* sgb1  = (const float*)d_in[16];
    const float* sgw2  = (const float*)d_in[17];
    const float* sgb2  = (const float*)d_in[18];
    float* out = (float*)d_out;

    float* out_res = out + 2 * NN * HD;   // layout: mu_new | sigma_new | residuals

    k_init<<<(NN * NN + 255) / 256, 256>>>();
    k_scatter<<<NE / 256, 256>>>(ei);
    k_count<<<NE / 256, 256>>>(ei);
    k_scan<<<2, 1024>>>();
    k_fill<<<NE / 256, 256>>>(ei, dist);
    k_nodeA<<<NN / 16, 128>>>(mu, sigma, msgw1, msgb1);
    k_res<<<NE / 256, 256>>>(ei, dist, out_res);
    k_edge<<<NE / 32, 128>>>(ei, dist, conf, ang, dep, msgw1, msgw2, msgb2);
    k_agg<<<NN, 128>>>();
    k_node<<<NN / 16, 128>>>(mu, muw1, mub1, muw2, mub2, sgw1, sgb1, sgw2, sgb2, out);
}

// round 3
// speedup vs baseline: 2.7574x; 1.2134x over previous
#include <cuda_runtime.h>
#include <math.h>
#include <stdint.h>

#define NN 2048
#define NE 32768
#define HD 128

// ---------------- scratch (static __device__, no allocation) ----------------
__device__ int   g_adj[NN * NN];
__device__ int   g_deg_src[NN];
__device__ int   g_cnt_dst[NN];
__device__ int   g_off_src[NN + 1];
__device__ int   g_off_dst[NN + 1];
__device__ int   g_cur_src[NN];
__device__ int   g_cur_dst[NN];
__device__ int   g_nb_col[NE];
__device__ float g_nb_val[NE];
__device__ int   g_in_edge[NE];
__device__ float g_A[NN * HD];
__device__ float g_res[NE];
__device__ float g_wgt[NE];
__device__ float g_wm[NE * HD];
__device__ float g_agg[NN * HD];
__device__ float g_meanr[NN];

// ---------------- 1: init ----------------
__global__ void k_init() {
    int i = blockIdx.x * blockDim.x + threadIdx.x;
    if (i < NN * NN) g_adj[i] = -1;
    if (i < NN) { g_deg_src[i] = 0; g_cnt_dst[i] = 0; g_cur_src[i] = 0; g_cur_dst[i] = 0; }
}

// ---------------- 2: scatter, last-write-wins ----------------
__global__ void k_scatter(const int* __restrict__ ei) {
    int e = blockIdx.x * blockDim.x + threadIdx.x;
    if (e >= NE) return;
    int s = ei[e], d = ei[NE + e];
    atomicMax(&g_adj[s * NN + d], e);
}

// ---------------- 3: degree counts ----------------
__global__ void k_count(const int* __restrict__ ei) {
    int e = blockIdx.x * blockDim.x + threadIdx.x;
    if (e >= NE) return;
    int s = ei[e], d = ei[NE + e];
    if (g_adj[s * NN + d] == e) atomicAdd(&g_deg_src[s], 1);
    atomicAdd(&g_cnt_dst[d], 1);
}

// ---------------- 4: parallel prefix scan ----------------
__global__ void __launch_bounds__(1024) k_scan() {
    const int* in = blockIdx.x ? g_cnt_dst : g_deg_src;
    int* off      = blockIdx.x ? g_off_dst : g_off_src;
    int t = threadIdx.x;
    int a = in[2 * t], b = in[2 * t + 1];
    int s = a + b;
    int lane = t & 31, wid = t >> 5;
    int v = s;
    #pragma unroll
    for (int o = 1; o < 32; o <<= 1) {
        int n = __shfl_up_sync(0xffffffffu, v, o);
        if (lane >= o) v += n;
    }
    __shared__ int wsum[32];
    if (lane == 31) wsum[wid] = v;
    __syncthreads();
    if (wid == 0) {
        int w = wsum[lane];
        #pragma unroll
        for (int o = 1; o < 32; o <<= 1) {
            int n = __shfl_up_sync(0xffffffffu, w, o);
            if (lane >= o) w += n;
        }
        wsum[lane] = w;
    }
    __syncthreads();
    int incl = v + (wid ? wsum[wid - 1] : 0);
    int excl = incl - s;
    off[2 * t]     = excl;
    off[2 * t + 1] = excl + a;
    if (t == 1023) off[2048] = incl;
}

// ---------------- 5: fill CSRs ----------------
__global__ void k_fill(const int* __restrict__ ei, const float* __restrict__ dist) {
    int e = blockIdx.x * blockDim.x + threadIdx.x;
    if (e >= NE) return;
    int s = ei[e], d = ei[NE + e];
    if (g_adj[s * NN + d] == e) {
        int p = atomicAdd(&g_cur_src[s], 1);
        int o = g_off_src[s] + p;
        g_nb_col[o] = d;
        g_nb_val[o] = dist[e];
    }
    int q = atomicAdd(&g_cur_dst[d], 1);
    g_in_edge[g_off_dst[d] + q] = e;
}

// ---------------- 6: per-node layer-1 pre-GEMM ----------------
__global__ void __launch_bounds__(128) k_nodeA(const float* __restrict__ mu,
                                               const float* __restrict__ sig,
                                               const float* __restrict__ w1,
                                               const float* __restrict__ b1) {
    __shared__ float xs[16][256];
    int t = threadIdx.x;
    int nb = blockIdx.x * 16;
    #pragma unroll
    for (int i = 0; i < 16; i++) {
        xs[i][t]       = mu[(nb + i) * HD + t];
        xs[i][128 + t] = sig[(nb + i) * HD + t];
    }
    __syncthreads();
    float acc[16];
    float b = b1[t];
    #pragma unroll
    for (int i = 0; i < 16; i++) acc[i] = b;
    #pragma unroll 4
    for (int k = 0; k < 256; k++) {
        float w = __ldg(&w1[k * HD + t]);
        #pragma unroll
        for (int i = 0; i < 16; i++) acc[i] += xs[i][k] * w;
    }
    #pragma unroll
    for (int i = 0; i < 16; i++) g_A[(nb + i) * HD + t] = acc[i];
}

// ---------------- 7: residuals via sparse two-hop probe ----------------
__global__ void k_res(const int* __restrict__ ei, const float* __restrict__ dist,
                      float* __restrict__ out_res) {
    int e = blockIdx.x * blockDim.x + threadIdx.x;
    if (e >= NE) return;
    int s = ei[e], d = ei[NE + e];
    float dac = dist[e];
    int beg = g_off_src[s], end = g_off_src[s + 1];
    float sum = 0.0f; int cnt = 0;
    for (int i = beg; i < end; i++) {
        int B = g_nb_col[i];
        float dab = g_nb_val[i];
        int idx = g_adj[B * NN + d];
        if (idx >= 0) { sum += dab + dist[idx]; cnt++; }
    }
    float mean = (cnt > 0) ? (sum / (float)cnt) : dac;
    float r = fabsf(dac - mean);
    g_res[e] = r;
    g_wgt[e] = expf(-r);
    out_res[e] = r;
}

// ---------------- 8: edge hidden + tf32 mma layer-2 + weighting ----------------
// 64 edges/block, 128 threads (4 warps). Stage1: hidden [64][128] fp32 relu in smem
// (row stride 132 -> A-fragment LDS conflict-free). Stage2: each warp computes the
// 64x32 output slab for its 32 columns via mma.sync.m16n8k8.tf32.
#define HPAD 132
__global__ void __launch_bounds__(128) k_edge(const int* __restrict__ ei,
                                              const float* __restrict__ dist,
                                              const float* __restrict__ conf,
                                              const float* __restrict__ ang,
                                              const float* __restrict__ dep,
                                              const float* __restrict__ w1,
                                              const float* __restrict__ w2,
                                              const float* __restrict__ b2) {
    __shared__ float hid[64 * HPAD];
    int t = threadIdx.x;
    int eb = blockIdx.x * 64;

    // stage 1: hidden = relu(A[src] + feats @ W1_feat)
    float wf0 = w1[(256) * HD + t];
    float wf1 = w1[(257) * HD + t];
    float wf2 = w1[(258) * HD + t];
    float wf3 = w1[(259) * HD + t];
    #pragma unroll 4
    for (int x = 0; x < 64; x++) {
        int e = eb + x;
        int s = ei[e];
        float v = g_A[s * HD + t]
                + dist[e] * wf0 + conf[e] * wf1 + ang[e] * wf2 + dep[e] * wf3;
        hid[x * HPAD + t] = fmaxf(v, 0.0f);
    }
    __syncthreads();

    // stage 2: tf32 mma. warp w covers output columns [32w, 32w+32)
    int warp = t >> 5;
    int lane = t & 31;
    int gid = lane >> 2;     // group id 0..7
    int tig = lane & 3;      // thread-in-group 0..3
    int n0 = warp * 32;

    float c[4][4][4];        // [m-tile][n-tile][frag]
    #pragma unroll
    for (int mt = 0; mt < 4; mt++)
        #pragma unroll
        for (int nt = 0; nt < 4; nt++)
            #pragma unroll
            for (int q = 0; q < 4; q++) c[mt][nt][q] = 0.0f;

    const uint32_t* hidu = (const uint32_t*)hid;

    #pragma unroll 2
    for (int kt = 0; kt < 16; kt++) {
        int k0 = kt * 8;
        // B fragments: b0 = W2[k0+tig][n], b1 = W2[k0+tig+4][n], n = n0+nt*8+gid
        uint32_t b0[4], b1[4];
        #pragma unroll
        for (int nt = 0; nt < 4; nt++) {
            int n = n0 + nt * 8 + gid;
            b0[nt] = __float_as_uint(__ldg(&w2[(k0 + tig) * HD + n]));
            b1[nt] = __float_as_uint(__ldg(&w2[(k0 + tig + 4) * HD + n]));
        }
        // A fragments per m-tile
        uint32_t a0[4], a1[4], a2[4], a3[4];
        #pragma unroll
        for (int mt = 0; mt < 4; mt++) {
            int r0 = mt * 16 + gid;
            a0[mt] = hidu[r0 * HPAD + k0 + tig];
            a1[mt] = hidu[(r0 + 8) * HPAD + k0 + tig];
            a2[mt] = hidu[r0 * HPAD + k0 + tig + 4];
            a3[mt] = hidu[(r0 + 8) * HPAD + k0 + tig + 4];
        }
        #pragma unroll
        for (int mt = 0; mt < 4; mt++)
            #pragma unroll
            for (int nt = 0; nt < 4; nt++) {
                asm volatile(
                    "mma.sync.aligned.m16n8k8.row.col.f32.tf32.tf32.f32 "
                    "{%0,%1,%2,%3}, {%4,%5,%6,%7}, {%8,%9}, {%0,%1,%2,%3};"
                    : "+f"(c[mt][nt][0]), "+f"(c[mt][nt][1]),
                      "+f"(c[mt][nt][2]), "+f"(c[mt][nt][3])
                    : "r"(a0[mt]), "r"(a1[mt]), "r"(a2[mt]), "r"(a3[mt]),
                      "r"(b0[nt]), "r"(b1[nt]));
            }
    }

    // epilogue: out = (C + b2) * wgt, scattered to g_wm
    #pragma unroll
    for (int nt = 0; nt < 4; nt++) {
        int n = n0 + nt * 8 + 2 * tig;
        float bb0 = __ldg(&b2[n]);
        float bb1 = __ldg(&b2[n + 1]);
        #pragma unroll
        for (int mt = 0; mt < 4; mt++) {
            int e0 = eb + mt * 16 + gid;
            int e1 = e0 + 8;
            float w0 = g_wgt[e0];
            float w1v = g_wgt[e1];
            float2 v0 = make_float2((c[mt][nt][0] + bb0) * w0, (c[mt][nt][1] + bb1) * w0);
            float2 v1 = make_float2((c[mt][nt][2] + bb0) * w1v, (c[mt][nt][3] + bb1) * w1v);
            *(float2*)&g_wm[e0 * HD + n] = v0;
            *(float2*)&g_wm[e1 * HD + n] = v1;
        }
    }
}

// ---------------- 9: deterministic segment aggregation by dst ----------------
__global__ void __launch_bounds__(128) k_agg() {
    int n = blockIdx.x;
    int t = threadIdx.x;
    int beg = g_off_dst[n], end = g_off_dst[n + 1];
    float acc = 0.0f, ws = 0.0f, rs = 0.0f;
    for (int i = beg; i < end; i++) {
        int e = g_in_edge[i];
        acc += g_wm[e * HD + t];
        ws  += g_wgt[e];
        rs  += g_res[e];
    }
    g_agg[n * HD + t] = acc / fmaxf(ws, 1e-8f);
    if (t == 0) g_meanr[n] = rs / fmaxf((float)(end - beg), 1.0f);
}

// ---------------- 10: node MLPs ----------------
__global__ void __launch_bounds__(128) k_node(const float* __restrict__ mu,
                                              const float* __restrict__ muw1, const float* __restrict__ mub1,
                                              const float* __restrict__ muw2, const float* __restrict__ mub2,
                                              const float* __restrict__ sgw1, const float* __restrict__ sgb1,
                                              const float* __restrict__ sgw2, const float* __restrict__ sgb2,
                                              float* __restrict__ out) {
    __shared__ float xs[16][128];
    __shared__ float ys[16][128];
    __shared__ float mr[16];
    int t = threadIdx.x;
    int nb = blockIdx.x * 16;
    #pragma unroll
    for (int i = 0; i < 16; i++) xs[i][t] = g_agg[(nb + i) * HD + t];
    if (t < 16) mr[t] = g_meanr[nb + t];
    __syncthreads();

    float acc[16];

    { float b = mub1[t];
      #pragma unroll
      for (int i = 0; i < 16; i++) acc[i] = b;
      #pragma unroll 4
      for (int k = 0; k < 128; k++) {
          float w = __ldg(&muw1[k * HD + t]);
          #pragma unroll
          for (int i = 0; i < 16; i++) acc[i] += xs[i][k] * w;
      } }
    #pragma unroll
    for (int i = 0; i < 16; i++) ys[i][t] = fmaxf(acc[i], 0.0f);
    __syncthreads();

    { float b = mub2[t];
      #pragma unroll
      for (int i = 0; i < 16; i++) acc[i] = b;
      #pragma unroll 4
      for (int k = 0; k < 128; k++) {
          float w = __ldg(&muw2[k * HD + t]);
          #pragma unroll
          for (int i = 0; i < 16; i++) acc[i] += ys[i][k] * w;
      }
      #pragma unroll
      for (int i = 0; i < 16; i++)
          out[(nb + i) * HD + t] = mu[(nb + i) * HD + t] + acc[i];
    }

    { float b = sgb1[t];
      float wlast = __ldg(&sgw1[128 * HD + t]);
      #pragma unroll
      for (int i = 0; i < 16; i++) acc[i] = b + mr[i] * wlast;
      #pragma unroll 4
      for (int k = 0; k < 128; k++) {
          float w = __ldg(&sgw1[k * HD + t]);
          #pragma unroll
          for (int i = 0; i < 16; i++) acc[i] += xs[i][k] * w;
      } }
    __syncthreads();
    #pragma unroll
    for (int i = 0; i < 16; i++) ys[i][t] = fmaxf(acc[i], 0.0f);
    __syncthreads();

    { float b = sgb2[t];
      #pragma unroll
      for (int i = 0; i < 16; i++) acc[i] = b;
      #pragma unroll 4
      for (int k = 0; k < 128; k++) {
          float w = __ldg(&sgw2[k * HD + t]);
          #pragma unroll
          for (int i = 0; i < 16; i++) acc[i] += ys[i][k] * w;
      }
      #pragma unroll
      for (int i = 0; i < 16; i++) {
          float x = acc[i];
          float sp = fmaxf(x, 0.0f) + log1pf(expf(-fabsf(x)));
          out[NN * HD + (nb + i) * HD + t] = sp;
      } }
}

// ---------------- launch ----------------
extern "C" void kernel_launch(void* const* d_in, const int* in_sizes, int n_in,
                              void* d_out, int out_size) {
    const float* mu    = (const float*)d_in[0];
    const float* sigma = (const float*)d_in[1];
    const int*   ei    = (const int*)d_in[2];
    const float* dist  = (const float*)d_in[3];
    const float* conf  = (const float*)d_in[4];
    const float* ang   = (const float*)d_in[5];
    const float* dep   = (const float*)d_in[6];
    const float* msgw1 = (const float*)d_in[7];
    const float* msgb1 = (const float*)d_in[8];
    const float* msgw2 = (const float*)d_in[9];
    const float* msgb2 = (const float*)d_in[10];
    const float* muw1  = (const float*)d_in[11];
    const float* mub1  = (const float*)d_in[12];
    const float* muw2  = (const float*)d_in[13];
    const float* mub2  = (const float*)d_in[14];
    const float* sgw1  = (const float*)d_in[15];
    const float* sgb1  = (const float*)d_in[16];
    const float* sgw2  = (const float*)d_in[17];
    const float* sgb2  = (const float*)d_in[18];
    float* out = (float*)d_out;

    float* out_res = out + 2 * NN * HD;

    k_init<<<(NN * NN + 255) / 256, 256>>>();
    k_scatter<<<NE / 256, 256>>>(ei);
    k_count<<<NE / 256, 256>>>(ei);
    k_scan<<<2, 1024>>>();
    k_fill<<<NE / 256, 256>>>(ei, dist);
    k_nodeA<<<NN / 16, 128>>>(mu, sigma, msgw1, msgb1);
    k_res<<<NE / 256, 256>>>(ei, dist, out_res);
    k_edge<<<NE / 64, 128>>>(ei, dist, conf, ang, dep, msgw1, msgw2, msgb2);
    k_agg<<<NN, 128>>>();
    k_node<<<NN / 16, 128>>>(mu, muw1, mub1, muw2, mub2, sgw1, sgb1, sgw2, sgb2, out);
}